// round 1
// baseline (speedup 1.0000x reference)
#include <cuda_runtime.h>
#include <math.h>

#define N_ATOMS 2048
#define HID     32
#define CUTOFF2 6.25f
#define JCHUNK  64

__device__ double g_energy;

__device__ __forceinline__ float tanh_fast(float x) {
    float y;
    asm("tanh.approx.f32 %0, %1;" : "=f"(y) : "f"(x));
    return y;
}

__global__ void zero_kernel() {
    g_energy = 0.0;
}

__global__ __launch_bounds__(256) void pair_kernel(
    const float* __restrict__ xyz,
    const float* __restrict__ cell,
    const float* __restrict__ W1,
    const float* __restrict__ b1,
    const float* __restrict__ W2,
    const float* __restrict__ b2)
{
    __shared__ float4 sj[JCHUNK];     // j-chunk positions (x,y,z,0)
    __shared__ float4 sw[HID];        // (W1[k], b1[k], W2[k], 0)
    __shared__ double swarp[8];

    const int tid = threadIdx.x;
    const int i   = blockIdx.x * blockDim.x + tid;   // 8 * 256 = 2048 i values
    const int j0  = blockIdx.y * JCHUNK;

    if (tid < JCHUNK) {
        int j = j0 + tid;
        sj[tid] = make_float4(xyz[3*j], xyz[3*j+1], xyz[3*j+2], 0.f);
    } else if (tid < JCHUNK + HID) {
        int k = tid - JCHUNK;
        sw[k] = make_float4(W1[k], b1[k], W2[k], 0.f);
    }
    __syncthreads();

    const float Lx = cell[0], Ly = cell[1], Lz = cell[2];
    const float iLx = 1.0f / Lx, iLy = 1.0f / Ly, iLz = 1.0f / Lz;
    const float xi = xyz[3*i], yi = xyz[3*i+1], zi = xyz[3*i+2];
    const float b2v = b2[0];

    double acc = 0.0;

    #pragma unroll 4
    for (int jj = 0; jj < JCHUNK; jj++) {
        float4 p = sj[jj];
        // d = xyz[j] - xyz[i], minimum image
        float dx = p.x - xi;
        float dy = p.y - yi;
        float dz = p.z - zi;
        dx = fmaf(-Lx, rintf(dx * iLx), dx);
        dy = fmaf(-Ly, rintf(dy * iLy), dy);
        dz = fmaf(-Lz, rintf(dz * iLz), dz);
        float dsq = fmaf(dx, dx, fmaf(dy, dy, dz * dz));

        if (dsq > 0.0f && dsq < CUTOFF2) {
            float dist = sqrtf(dsq);
            float e = b2v;
            #pragma unroll
            for (int k = 0; k < HID; k++) {
                float4 w = sw[k];
                float h = tanh_fast(fmaf(dist, w.x, w.y));
                e = fmaf(h, w.z, e);
            }
            acc += (double)e;
        }
    }

    // warp reduce (double)
    #pragma unroll
    for (int off = 16; off > 0; off >>= 1)
        acc += __shfl_down_sync(0xFFFFFFFFu, acc, off);

    const int lane = tid & 31;
    const int warp = tid >> 5;
    if (lane == 0) swarp[warp] = acc;
    __syncthreads();

    if (warp == 0) {
        double v = (lane < 8) ? swarp[lane] : 0.0;
        #pragma unroll
        for (int off = 4; off > 0; off >>= 1)
            v += __shfl_down_sync(0xFFFFFFFFu, v, off);
        if (lane == 0)
            atomicAdd(&g_energy, v);
    }
}

__global__ void finalize_kernel(float* out) {
    // ordered-pair sum double-counts each unordered pair
    out[0] = (float)(0.5 * g_energy);
}

extern "C" void kernel_launch(void* const* d_in, const int* in_sizes, int n_in,
                              void* d_out, int out_size)
{
    const float* xyz  = (const float*)d_in[0];
    const float* cell = (const float*)d_in[1];
    const float* W1   = (const float*)d_in[2];
    const float* b1   = (const float*)d_in[3];
    const float* W2   = (const float*)d_in[4];
    const float* b2   = (const float*)d_in[5];
    float* out = (float*)d_out;

    zero_kernel<<<1, 1>>>();
    dim3 grid(N_ATOMS / 256, N_ATOMS / JCHUNK);   // 8 x 32 = 256 blocks
    pair_kernel<<<grid, 256>>>(xyz, cell, W1, b1, W2, b2);
    finalize_kernel<<<1, 1>>>(out);
}

// round 2
// speedup vs baseline: 2.4527x; 2.4527x over previous
#include <cuda_runtime.h>
#include <math.h>

#define N_ATOMS 2048
#define HID     32
#define CUTOFF  2.5f
#define CUTOFF2 6.25f
#define JCHUNK  64
#define LUT_N   4096

__device__ double   g_energy = 0.0;
__device__ unsigned g_done   = 0;
__device__ float2   g_lut[LUT_N];

__device__ __forceinline__ float tanh_fast(float x) {
    float y;
    asm("tanh.approx.f32 %0, %1;" : "=f"(y) : "f"(x));
    return y;
}

// Build LUT of f(d) = sum_k W2[k]*tanh(W1[k]*d + b1[k]) + b2 on [0, CUTOFF].
// Entry i stores (f(x_i), f(x_{i+1}) - f(x_i)) for one-LDS.64 lerp.
__global__ __launch_bounds__(256) void lut_kernel(
    const float* __restrict__ W1, const float* __restrict__ b1,
    const float* __restrict__ W2, const float* __restrict__ b2)
{
    const int idx = blockIdx.x * blockDim.x + threadIdx.x;
    if (idx >= LUT_N) return;
    const float dx = CUTOFF / (float)LUT_N;
    const float x0 = (float)idx * dx;
    const float x1 = x0 + dx;
    float f0 = b2[0], f1 = b2[0];
    #pragma unroll
    for (int k = 0; k < HID; k++) {
        float w1 = W1[k], bb = b1[k], w2 = W2[k];
        f0 = fmaf(tanh_fast(fmaf(x0, w1, bb)), w2, f0);
        f1 = fmaf(tanh_fast(fmaf(x1, w1, bb)), w2, f1);
    }
    g_lut[idx] = make_float2(f0, f1 - f0);
}

__global__ __launch_bounds__(256) void pair_kernel(
    const float* __restrict__ xyz,
    const float* __restrict__ cell,
    float* __restrict__ out)
{
    __shared__ float4 sj[JCHUNK];
    __shared__ float2 s_lut[LUT_N];   // 32 KB
    __shared__ double swarp[8];

    const int tid = threadIdx.x;
    const int i   = blockIdx.x * blockDim.x + tid;     // 8 * 256 = 2048
    const int j0  = blockIdx.y * JCHUNK;

    // cache j-chunk positions
    if (tid < JCHUNK) {
        int j = j0 + tid;
        sj[tid] = make_float4(xyz[3*j], xyz[3*j+1], xyz[3*j+2], 0.f);
    }
    // copy LUT to smem as float4 (2048 float4 / 256 threads = 8 each)
    {
        const float4* src = (const float4*)g_lut;
        float4*       dst = (float4*)s_lut;
        #pragma unroll
        for (int t = tid; t < LUT_N / 2; t += 256)
            dst[t] = src[t];
    }
    __syncthreads();

    const float Lx = cell[0], Ly = cell[1], Lz = cell[2];
    const float iLx = 1.0f / Lx, iLy = 1.0f / Ly, iLz = 1.0f / Lz;
    const float xi = xyz[3*i], yi = xyz[3*i+1], zi = xyz[3*i+2];
    const float lscale = (float)LUT_N / CUTOFF;

    float acc = 0.0f;

    #pragma unroll 4
    for (int jj = 0; jj < JCHUNK; jj++) {
        float4 p = sj[jj];
        float dx = p.x - xi;
        float dy = p.y - yi;
        float dz = p.z - zi;
        dx = fmaf(-Lx, rintf(dx * iLx), dx);
        dy = fmaf(-Ly, rintf(dy * iLy), dy);
        dz = fmaf(-Lz, rintf(dz * iLz), dz);
        float dsq = fmaf(dx, dx, fmaf(dy, dy, dz * dz));

        if (dsq > 0.0f && dsq < CUTOFF2) {
            float dist = dsq * rsqrtf(dsq);       // MUFU sqrt
            float t = dist * lscale;              // t < 4096
            int   it = (int)t;
            float fr = t - (float)it;
            float2 e = s_lut[it];
            acc += fmaf(fr, e.y, e.x);
        }
    }

    // warp reduce in double
    double dv = (double)acc;
    #pragma unroll
    for (int off = 16; off > 0; off >>= 1)
        dv += __shfl_down_sync(0xFFFFFFFFu, dv, off);

    const int lane = tid & 31;
    const int warp = tid >> 5;
    if (lane == 0) swarp[warp] = dv;
    __syncthreads();

    if (warp == 0) {
        double v = (lane < 8) ? swarp[lane] : 0.0;
        #pragma unroll
        for (int off = 4; off > 0; off >>= 1)
            v += __shfl_down_sync(0xFFFFFFFFu, v, off);
        if (lane == 0) {
            atomicAdd(&g_energy, v);
            __threadfence();
            unsigned total = gridDim.x * gridDim.y;
            unsigned old = atomicAdd(&g_done, 1);
            if (old == total - 1) {
                __threadfence();
                // atomically read-and-reset accumulator (replay determinism)
                double esum = __longlong_as_double(
                    atomicExch((unsigned long long*)&g_energy, 0ULL));
                out[0] = (float)(0.5 * esum);   // ordered pairs double-count
                __threadfence();
                atomicExch(&g_done, 0u);
            }
        }
    }
}

extern "C" void kernel_launch(void* const* d_in, const int* in_sizes, int n_in,
                              void* d_out, int out_size)
{
    const float* xyz  = (const float*)d_in[0];
    const float* cell = (const float*)d_in[1];
    const float* W1   = (const float*)d_in[2];
    const float* b1   = (const float*)d_in[3];
    const float* W2   = (const float*)d_in[4];
    const float* b2   = (const float*)d_in[5];
    float* out = (float*)d_out;

    lut_kernel<<<LUT_N / 256, 256>>>(W1, b1, W2, b2);
    dim3 grid(N_ATOMS / 256, N_ATOMS / JCHUNK);   // 8 x 32 = 256 blocks
    pair_kernel<<<grid, 256>>>(xyz, cell, out);
}

// round 3
// speedup vs baseline: 2.4573x; 1.0019x over previous
#include <cuda_runtime.h>
#include <math.h>

#define N_ATOMS 2048
#define HID     32
#define CUTOFF  2.5f
#define CUTOFF2 6.25f
#define JCHUNK  16
#define LUT_N   4096

__device__ double   g_energy = 0.0;
__device__ unsigned g_done   = 0;
__device__ float2   g_lut[LUT_N];

__device__ __forceinline__ float tanh_fast(float x) {
    float y;
    asm("tanh.approx.f32 %0, %1;" : "=f"(y) : "f"(x));
    return y;
}

// Build LUT of f(d) = sum_k W2[k]*tanh(W1[k]*d + b1[k]) + b2 on [0, CUTOFF].
// Entry i stores (f(x_i), f(x_{i+1}) - f(x_i)) for a single-load lerp.
__global__ __launch_bounds__(256) void lut_kernel(
    const float* __restrict__ W1, const float* __restrict__ b1,
    const float* __restrict__ W2, const float* __restrict__ b2)
{
    const int idx = blockIdx.x * blockDim.x + threadIdx.x;
    if (idx >= LUT_N) return;
    const float dx = CUTOFF / (float)LUT_N;
    const float x0 = (float)idx * dx;
    const float x1 = x0 + dx;
    float f0 = b2[0], f1 = b2[0];
    #pragma unroll
    for (int k = 0; k < HID; k++) {
        float w1 = W1[k], bb = b1[k], w2 = W2[k];
        f0 = fmaf(tanh_fast(fmaf(x0, w1, bb)), w2, f0);
        f1 = fmaf(tanh_fast(fmaf(x1, w1, bb)), w2, f1);
    }
    g_lut[idx] = make_float2(f0, f1 - f0);
}

__global__ __launch_bounds__(256) void pair_kernel(
    const float* __restrict__ xyz,
    const float* __restrict__ cell,
    float* __restrict__ out)
{
    __shared__ float4 sj[JCHUNK];
    __shared__ double swarp[8];

    const int tid = threadIdx.x;
    const int i   = blockIdx.x * blockDim.x + tid;     // 8 * 256 = 2048
    const int j0  = blockIdx.y * JCHUNK;

    if (tid < JCHUNK) {
        int j = j0 + tid;
        sj[tid] = make_float4(xyz[3*j], xyz[3*j+1], xyz[3*j+2], 0.f);
    }
    __syncthreads();

    const float Lx = cell[0], Ly = cell[1], Lz = cell[2];
    const float iLx = 1.0f / Lx, iLy = 1.0f / Ly, iLz = 1.0f / Lz;
    const float xi = xyz[3*i], yi = xyz[3*i+1], zi = xyz[3*i+2];
    const float lscale = (float)LUT_N / CUTOFF;

    float acc = 0.0f;

    #pragma unroll
    for (int jj = 0; jj < JCHUNK; jj++) {
        float4 p = sj[jj];
        float dx = p.x - xi;
        float dy = p.y - yi;
        float dz = p.z - zi;
        dx = fmaf(-Lx, rintf(dx * iLx), dx);
        dy = fmaf(-Ly, rintf(dy * iLy), dy);
        dz = fmaf(-Lz, rintf(dz * iLz), dz);
        float dsq = fmaf(dx, dx, fmaf(dy, dy, dz * dz));

        if (dsq > 0.0f && dsq < CUTOFF2) {
            float dist = dsq * rsqrtf(dsq);       // MUFU sqrt
            float t = dist * lscale;              // < 4096
            int   it = (int)t;
            float fr = t - (float)it;
            float2 e = __ldg(&g_lut[it]);         // L1-resident (32 KB)
            acc += fmaf(fr, e.y, e.x);
        }
    }

    // warp reduce in double
    double dv = (double)acc;
    #pragma unroll
    for (int off = 16; off > 0; off >>= 1)
        dv += __shfl_down_sync(0xFFFFFFFFu, dv, off);

    const int lane = tid & 31;
    const int warp = tid >> 5;
    if (lane == 0) swarp[warp] = dv;
    __syncthreads();

    if (warp == 0) {
        double v = (lane < 8) ? swarp[lane] : 0.0;
        #pragma unroll
        for (int off = 4; off > 0; off >>= 1)
            v += __shfl_down_sync(0xFFFFFFFFu, v, off);
        if (lane == 0) {
            atomicAdd(&g_energy, v);
            __threadfence();
            unsigned total = gridDim.x * gridDim.y;
            unsigned old = atomicAdd(&g_done, 1);
            if (old == total - 1) {
                __threadfence();
                double esum = __longlong_as_double(
                    atomicExch((unsigned long long*)&g_energy, 0ULL));
                out[0] = (float)(0.5 * esum);   // ordered pairs double-count
                __threadfence();
                atomicExch(&g_done, 0u);
            }
        }
    }
}

extern "C" void kernel_launch(void* const* d_in, const int* in_sizes, int n_in,
                              void* d_out, int out_size)
{
    const float* xyz  = (const float*)d_in[0];
    const float* cell = (const float*)d_in[1];
    const float* W1   = (const float*)d_in[2];
    const float* b1   = (const float*)d_in[3];
    const float* W2   = (const float*)d_in[4];
    const float* b2   = (const float*)d_in[5];
    float* out = (float*)d_out;

    lut_kernel<<<LUT_N / 256, 256>>>(W1, b1, W2, b2);
    dim3 grid(N_ATOMS / 256, N_ATOMS / JCHUNK);   // 8 x 128 = 1024 blocks
    pair_kernel<<<grid, 256>>>(xyz, cell, out);
}